// round 6
// baseline (speedup 1.0000x reference)
#include <cuda_runtime.h>
#include <math.h>

// Shapes fixed by reference: [2,4,32,64,64]
constexpr int Cc    = 32;          // channels
constexpr int HW    = 4096;        // 64*64 positions
constexpr int NI    = 8;           // B*L items
constexpr int BPI   = 128;         // blocks per item (TP=32)
constexpr int TP    = 32;          // positions per block
constexpr int PITCH = 36;          // 9 x 16B rows: LDS.128-aligned, odd quad-bank stride
constexpr int TH1   = 192;         // 3 groups x 64 threads
constexpr int NREP  = 8;           // atomic accumulator replicas

// Replicated accumulators: [replica][item][mat][32*32]. Zero-initialized at
// module load; k_final re-zeroes after reading so every graph replay starts at 0.
__device__ float g_acc[(size_t)NREP * NI * 3 * 1024];

// Physical row for logical channel c: spreads both 8-strided row sets used by
// the main loop across all 8 quad-banks (conflict-free LDS.128).
__device__ __forceinline__ int rowmap(int c) { return ((c & 3) << 3) | (c >> 2); }

__global__ __launch_bounds__(TH1, 5) void k_partial(const float* __restrict__ S,
                                                    const float* __restrict__ T,
                                                    float* __restrict__ out) {
    __shared__ __align__(16) float sS[Cc * PITCH];
    __shared__ __align__(16) float sT[Cc * PITCH];
    __shared__ __align__(16) float wgt[3 * TP];   // wA | wB | wM

    const int n   = blockIdx.y;
    const int blk = blockIdx.x;
    const int tid = threadIdx.x;
    const int p0  = blk * TP;

    // One thread zeroes the output each replay (graph edge orders this
    // before k_final's atomic adds).
    if (blk == 0 && n == 0 && tid == 0) *out = 0.f;

    const float4* __restrict__ Sb4 = (const float4*)(S + (size_t)n * Cc * HW);
    const float4* __restrict__ Tb4 = (const float4*)(T + (size_t)n * Cc * HW);

    // ---- Load tile [32 x 32] as float4, rows permuted ----
#pragma unroll
    for (int v = tid; v < Cc * (TP / 4); v += TH1) {
        const int c = v >> 3;          // logical channel
        const int q = v & 7;           // float4 index within row
        const int pr = rowmap(c);
        const float4 a = Sb4[(size_t)c * (HW / 4) + (p0 >> 2) + q];
        const float4 b = Tb4[(size_t)c * (HW / 4) + (p0 >> 2) + q];
        *(float4*)&sS[pr * PITCH + 4 * q] = a;
        *(float4*)&sT[pr * PITCH + 4 * q] = b;
    }
    __syncthreads();

    // ---- Per-position weights (norms folded): wA=ivT^2, wB=ivS^2, wM=ivS*ivT ----
    if (tid < TP) {
        const int p = tid;
        float ss = 0.f, st = 0.f;
#pragma unroll
        for (int r = 0; r < Cc; ++r) {
            const float a = sS[r * PITCH + p];
            const float b = sT[r * PITCH + p];
            ss = fmaf(a, a, ss);
            st = fmaf(b, b, st);
        }
        const float ivS = 1.f / (sqrtf(ss) + 1e-8f);
        const float ivT = 1.f / (sqrtf(st) + 1e-8f);
        wgt[0 * TP + p] = ivT * ivT;
        wgt[1 * TP + p] = ivS * ivS;
        wgt[2 * TP + p] = ivS * ivT;
    }
    __syncthreads();

    // ---- Gram accumulation with weight folding ----
    // group = tid>>6: 0 -> A (T.T^t), 1 -> B (S.S^t), 2 -> M (S.T^t)
    const int grp = tid >> 6;
    const int lt  = tid & 63;
    const int ii  = lt >> 3;           // 0..7
    const int jj  = lt & 7;            // 0..7

    const float* __restrict__ Xi = (grp == 0) ? sT : sS;
    const float* __restrict__ Xj = (grp == 1) ? sS : sT;
    const float* xiB = Xi + ii * PITCH;   // + (8*rr)*PITCH + p (immediates)
    const float* xjB = Xj + jj * PITCH;
    const float* wB  = wgt + grp * TP;

    unsigned long long acc2[16];
#pragma unroll
    for (int k = 0; k < 16; ++k) acc2[k] = 0ull;

#pragma unroll
    for (int p = 0; p < TP; p += 4) {
        const float4 w4 = *(const float4*)&wB[p];           // broadcast
        const unsigned long long wL = *(const unsigned long long*)&w4.x;
        const unsigned long long wH = *(const unsigned long long*)&w4.z;

        float4 xi4[4], xj4[4];
#pragma unroll
        for (int rr = 0; rr < 4; ++rr) xi4[rr] = *(const float4*)&xiB[(8 * rr) * PITCH + p];
#pragma unroll
        for (int qq = 0; qq < 4; ++qq) xj4[qq] = *(const float4*)&xjB[(8 * qq) * PITCH + p];

        unsigned long long xiL[4], xiH[4];
#pragma unroll
        for (int rr = 0; rr < 4; ++rr) {
            unsigned long long a = *(const unsigned long long*)&xi4[rr].x;
            unsigned long long b = *(const unsigned long long*)&xi4[rr].z;
            asm("mul.rn.f32x2 %0, %0, %1;" : "+l"(a) : "l"(wL));
            asm("mul.rn.f32x2 %0, %0, %1;" : "+l"(b) : "l"(wH));
            xiL[rr] = a; xiH[rr] = b;
        }
#pragma unroll
        for (int rr = 0; rr < 4; ++rr) {
#pragma unroll
            for (int qq = 0; qq < 4; ++qq) {
                const unsigned long long xjL = *(const unsigned long long*)&xj4[qq].x;
                const unsigned long long xjH = *(const unsigned long long*)&xj4[qq].z;
                asm("fma.rn.f32x2 %0, %1, %2, %0;"
                    : "+l"(acc2[rr * 4 + qq]) : "l"(xiL[rr]), "l"(xjL));
                asm("fma.rn.f32x2 %0, %1, %2, %0;"
                    : "+l"(acc2[rr * 4 + qq]) : "l"(xiH[rr]), "l"(xjH));
            }
        }
    }

    // ---- Fire-and-forget accumulation into replicated slot ----
    const int rep = blk & (NREP - 1);
    float* dst = g_acc + ((size_t)(rep * NI + n) * 3 + grp) * 1024;
#pragma unroll
    for (int rr = 0; rr < 4; ++rr) {
#pragma unroll
        for (int qq = 0; qq < 4; ++qq) {
            const float2 v = *(const float2*)&acc2[rr * 4 + qq];
            atomicAdd(&dst[(4 * ii + rr) * 32 + 4 * jj + qq], v.x + v.y);
        }
    }
}

// 96 blocks x 256 threads: one thread per Gram element. Sum the 8 replicas,
// square, weight (-2 for M), zero replicas for next replay, reduce, atomic-add
// the scaled block sum into *out.
__global__ __launch_bounds__(256) void k_final(float* __restrict__ out) {
    const int gid = blockIdx.x * 256 + threadIdx.x;   // 0..24575
    const int rem = gid % 3072;                       // mat*1024 + el
    const int n   = gid / 3072;
    const int mat = rem >> 10;
    const int t   = threadIdx.x;

    float v = 0.f;
#pragma unroll
    for (int r = 0; r < NREP; ++r)
        v += g_acc[((size_t)(r * NI + n) * 3072) + rem];
#pragma unroll
    for (int r = 0; r < NREP; ++r)
        g_acc[((size_t)(r * NI + n) * 3072) + rem] = 0.f;

    const float contrib = (mat == 2) ? -2.f * v * v : v * v;

    __shared__ float red[256];
    red[t] = contrib;
    __syncthreads();
    for (int off = 128; off > 0; off >>= 1) {
        if (t < off) red[t] += red[t + off];
        __syncthreads();
    }
    // loss = total / (HW^2) / (B*L)
    if (t == 0) atomicAdd(out, red[0] * (1.f / (16777216.f * 8.f)));
}

extern "C" void kernel_launch(void* const* d_in, const int* in_sizes, int n_in,
                              void* d_out, int out_size) {
    const float* S = (const float*)d_in[0];
    const float* T = (const float*)d_in[1];
    (void)in_sizes; (void)n_in; (void)out_size;

    dim3 g1(BPI, NI);
    k_partial<<<g1, TH1>>>(S, T, (float*)d_out);
    k_final<<<96, 256>>>((float*)d_out);
}

// round 7
// speedup vs baseline: 1.0549x; 1.0549x over previous
#include <cuda_runtime.h>
#include <math.h>

// Shapes fixed by reference: [2,4,32,64,64]
constexpr int Cc    = 32;          // channels
constexpr int HW    = 4096;        // 64*64 positions
constexpr int NI    = 8;           // B*L items
constexpr int BPI   = 64;          // blocks per item (2 subtiles of 32 each)
constexpr int TP    = 32;          // positions per subtile
constexpr int PITCH = 36;          // 9 x 16B rows: LDS.128-aligned, odd quad-bank stride
constexpr int TH1   = 192;         // 3 groups x 64 threads
constexpr int NREP  = 8;           // atomic accumulator replicas

// Replicated accumulators: [replica][item][mat][32*32]. Zero at module load;
// k_final re-zeroes after reading so every graph replay starts clean.
__device__ float g_acc[(size_t)NREP * NI * 3 * 1024];

// Physical row for logical channel c: spreads the 8-strided row sets used by
// the main loop across all 8 quad-banks (conflict-free LDS.128).
__device__ __forceinline__ int rowmap(int c) { return ((c & 3) << 3) | (c >> 2); }

__global__ __launch_bounds__(TH1) void k_partial(const float* __restrict__ S,
                                                 const float* __restrict__ T,
                                                 float* __restrict__ out) {
    __shared__ __align__(16) float sS[2][Cc * PITCH];
    __shared__ __align__(16) float sT[2][Cc * PITCH];
    __shared__ __align__(16) float ivS[2][TP];
    __shared__ __align__(16) float ivT[2][TP];
    __shared__ __align__(16) float wgt[2][3 * TP];   // wA | wB | wM per subtile

    const int n   = blockIdx.y;
    const int blk = blockIdx.x;
    const int tid = threadIdx.x;

    if (blk == 0 && n == 0 && tid == 0) *out = 0.f;   // ordered before k_final by graph edge

    const float4* __restrict__ Sb4 = (const float4*)(S + (size_t)n * Cc * HW);
    const float4* __restrict__ Tb4 = (const float4*)(T + (size_t)n * Cc * HW);

    // Per-thread load slots: 256 float4-pairs per subtile, 192 threads -> slots tid, tid+192
    const int p0 = blk * 2 * TP;     // first position of subtile 0

    // thread's (channel,quad) for slot v: c=v>>3, q=v&7
    const int c0 = tid >> 3,          q0 = tid & 7;
    const int v1 = tid + TH1;
    const int c1 = (v1 < 256) ? (v1 >> 3) : 0, q1 = (v1 < 256) ? (v1 & 7) : 0;
    const bool has1 = (v1 < 256);

    // ---- Prefetch subtile 0 ----
    float4 a0 = Sb4[(size_t)c0 * (HW / 4) + (p0 >> 2) + q0];
    float4 b0 = Tb4[(size_t)c0 * (HW / 4) + (p0 >> 2) + q0];
    float4 a1 = {}, b1 = {};
    if (has1) {
        a1 = Sb4[(size_t)c1 * (HW / 4) + (p0 >> 2) + q1];
        b1 = Tb4[(size_t)c1 * (HW / 4) + (p0 >> 2) + q1];
    }

    // Group decomposition for main loop
    const int grp = tid >> 6;          // 0:A(T.T^t) 1:B(S.S^t) 2:M(S.T^t)
    const int lt  = tid & 63;
    const int ii  = lt >> 3;           // 0..7
    const int jj  = lt & 7;            // 0..7

    unsigned long long acc2[16];
#pragma unroll
    for (int k = 0; k < 16; ++k) acc2[k] = 0ull;

#pragma unroll
    for (int t = 0; t < 2; ++t) {
        // ---- Store current subtile to smem (row-permuted) ----
        *(float4*)&sS[t][rowmap(c0) * PITCH + 4 * q0] = a0;
        *(float4*)&sT[t][rowmap(c0) * PITCH + 4 * q0] = b0;
        if (has1) {
            *(float4*)&sS[t][rowmap(c1) * PITCH + 4 * q1] = a1;
            *(float4*)&sT[t][rowmap(c1) * PITCH + 4 * q1] = b1;
        }

        // ---- Prefetch next subtile while this one is processed ----
        if (t == 0) {
            const int pn = p0 + TP;
            a0 = Sb4[(size_t)c0 * (HW / 4) + (pn >> 2) + q0];
            b0 = Tb4[(size_t)c0 * (HW / 4) + (pn >> 2) + q0];
            if (has1) {
                a1 = Sb4[(size_t)c1 * (HW / 4) + (pn >> 2) + q1];
                b1 = Tb4[(size_t)c1 * (HW / 4) + (pn >> 2) + q1];
            }
        }
        __syncthreads();

        // ---- Norms: warp0 -> ivS, warp1 -> ivT (parallel chains) ----
        if (tid < TP) {
            const int p = tid;
            float ss = 0.f;
#pragma unroll
            for (int r = 0; r < Cc; ++r) { const float v = sS[t][r * PITCH + p]; ss = fmaf(v, v, ss); }
            ivS[t][p] = 1.f / (sqrtf(ss) + 1e-8f);
        } else if (tid < 2 * TP) {
            const int p = tid - TP;
            float st = 0.f;
#pragma unroll
            for (int r = 0; r < Cc; ++r) { const float v = sT[t][r * PITCH + p]; st = fmaf(v, v, st); }
            ivT[t][p] = 1.f / (sqrtf(st) + 1e-8f);
        }
        __syncthreads();
        if (tid < TP) {
            const float s = ivS[t][tid], w = ivT[t][tid];
            wgt[t][0 * TP + tid] = w * w;
            wgt[t][1 * TP + tid] = s * s;
            wgt[t][2 * TP + tid] = s * w;
        }
        __syncthreads();

        // ---- Gram accumulation (weights folded into xi) ----
        const float* __restrict__ Xi = (grp == 0) ? sT[t] : sS[t];
        const float* __restrict__ Xj = (grp == 1) ? sS[t] : sT[t];
        const float* xiB = Xi + ii * PITCH;
        const float* xjB = Xj + jj * PITCH;
        const float* wB  = wgt[t] + grp * TP;

#pragma unroll
        for (int p = 0; p < TP; p += 4) {
            const float4 w4 = *(const float4*)&wB[p];          // broadcast
            const unsigned long long wL = *(const unsigned long long*)&w4.x;
            const unsigned long long wH = *(const unsigned long long*)&w4.z;

            float4 xi4[4], xj4[4];
#pragma unroll
            for (int rr = 0; rr < 4; ++rr) xi4[rr] = *(const float4*)&xiB[(8 * rr) * PITCH + p];
#pragma unroll
            for (int qq = 0; qq < 4; ++qq) xj4[qq] = *(const float4*)&xjB[(8 * qq) * PITCH + p];

            unsigned long long xiL[4], xiH[4];
#pragma unroll
            for (int rr = 0; rr < 4; ++rr) {
                unsigned long long x = *(const unsigned long long*)&xi4[rr].x;
                unsigned long long y = *(const unsigned long long*)&xi4[rr].z;
                asm("mul.rn.f32x2 %0, %0, %1;" : "+l"(x) : "l"(wL));
                asm("mul.rn.f32x2 %0, %0, %1;" : "+l"(y) : "l"(wH));
                xiL[rr] = x; xiH[rr] = y;
            }
#pragma unroll
            for (int rr = 0; rr < 4; ++rr) {
#pragma unroll
                for (int qq = 0; qq < 4; ++qq) {
                    const unsigned long long xjL = *(const unsigned long long*)&xj4[qq].x;
                    const unsigned long long xjH = *(const unsigned long long*)&xj4[qq].z;
                    asm("fma.rn.f32x2 %0, %1, %2, %0;"
                        : "+l"(acc2[rr * 4 + qq]) : "l"(xiL[rr]), "l"(xjL));
                    asm("fma.rn.f32x2 %0, %1, %2, %0;"
                        : "+l"(acc2[rr * 4 + qq]) : "l"(xiH[rr]), "l"(xjH));
                }
            }
        }
        // No barrier needed after main: next iteration's STS targets buffer t=1.
    }

    // ---- Fire-and-forget accumulation into replicated slot ----
    const int rep = blk & (NREP - 1);
    float* dst = g_acc + ((size_t)(rep * NI + n) * 3 + grp) * 1024;
#pragma unroll
    for (int rr = 0; rr < 4; ++rr) {
#pragma unroll
        for (int qq = 0; qq < 4; ++qq) {
            const float2 v = *(const float2*)&acc2[rr * 4 + qq];
            atomicAdd(&dst[(4 * ii + rr) * 32 + 4 * jj + qq], v.x + v.y);
        }
    }
}

// 24 blocks x 1024 threads: exactly one thread per Gram element (8*3*1024).
// Coalesced replica loads, warp-shuffle reduce, one atomicAdd per block.
__global__ __launch_bounds__(1024) void k_final(float* __restrict__ out) {
    const int t   = threadIdx.x;
    const int gid = blockIdx.x * 1024 + t;            // 0..24575
    const int n   = gid / 3072;
    const int rem = gid % 3072;                       // mat*1024 + el
    const int mat = rem >> 10;

    float v = 0.f;
#pragma unroll
    for (int r = 0; r < NREP; ++r)
        v += g_acc[(size_t)(r * NI + n) * 3072 + rem];
#pragma unroll
    for (int r = 0; r < NREP; ++r)
        g_acc[(size_t)(r * NI + n) * 3072 + rem] = 0.f;

    float contrib = (mat == 2) ? -2.f * v * v : v * v;

    // Warp reduce
#pragma unroll
    for (int off = 16; off > 0; off >>= 1)
        contrib += __shfl_down_sync(0xffffffffu, contrib, off);

    __shared__ float wsum[32];
    if ((t & 31) == 0) wsum[t >> 5] = contrib;
    __syncthreads();

    if (t < 32) {
        float s = wsum[t];
#pragma unroll
        for (int off = 16; off > 0; off >>= 1)
            s += __shfl_down_sync(0xffffffffu, s, off);
        // loss = total / (HW^2) / (B*L)
        if (t == 0) atomicAdd(out, s * (1.f / (16777216.f * 8.f)));
    }
}

extern "C" void kernel_launch(void* const* d_in, const int* in_sizes, int n_in,
                              void* d_out, int out_size) {
    const float* S = (const float*)d_in[0];
    const float* T = (const float*)d_in[1];
    (void)in_sizes; (void)n_in; (void)out_size;

    dim3 g1(BPI, NI);
    k_partial<<<g1, TH1>>>(S, T, (float*)d_out);
    k_final<<<24, 1024>>>((float*)d_out);
}